// round 3
// baseline (speedup 1.0000x reference)
#include <cuda_runtime.h>
#include <math.h>

// Problem constants
#define DIMC   64
#define WINS   4
#define LTOK   36
#define DHD    8

typedef unsigned long long ull;

// Scratch: dynamic conv weights, layout [win][ci][tap][co]  (co contiguous)
__device__ __align__(16) float g_weights[WINS * 64 * 9 * 64];

// ---- packed f32x2 helpers -------------------------------------------------
#define FMA2(acc, a, b) \
    asm("fma.rn.f32x2 %0, %1, %2, %0;" : "+l"(acc) : "l"(a), "l"(b))
#define DUP2(d, f) \
    asm("mov.b64 %0, {%1, %1};" : "=l"(d) : "r"(__float_as_uint(f)))
#define UNPACK2(lo, hi, v) \
    asm("mov.b64 {%0, %1}, %2;" : "=r"(lo), "=r"(hi) : "l"(v))

// ===========================================================================
// Kernel A: build dynamic conv kernels (attention over 36 tokens + SE gate)
// one block per o (conv output channel), 288 threads.  ~microseconds.
// ===========================================================================
__global__ void __launch_bounds__(288) gen_kernels(
    const float* __restrict__ conv_w,  // (4,64,64,3,3)
    const float* __restrict__ w_qkv,   // (192,64)
    const float* __restrict__ b_qkv,   // (192)
    const float* __restrict__ w_out,   // (64,64)
    const float* __restrict__ b_out,   // (64)
    const float* __restrict__ se_w1,   // (4,4,64)
    const float* __restrict__ se_b1,   // (4,4)
    const float* __restrict__ se_w2,   // (4,64,4)
    const float* __restrict__ se_b2)   // (4,64)
{
    __shared__ float sm_a[LTOK * 64];
    __shared__ float sm_qkv[LTOK * 192];
    __shared__ float sm_k1[LTOK * 64];
    __shared__ float sm_pooled[64];
    __shared__ float sm_h1[4];

    const int o = blockIdx.x;
    const int t = threadIdx.x;

    // Phase 1: kern0[l][i] = conv_w[w][o][i][p], l = w*9+p
    for (int idx = t; idx < LTOK * 64; idx += 288) {
        int l = idx >> 6, i = idx & 63;
        int w_ = l / 9, p = l - w_ * 9;
        sm_a[idx] = conv_w[(((w_ * 64 + o) * 64 + i) * 9) + p];
    }
    __syncthreads();

    // Phase 2: qkv projection
    if (t < 192) {
        float wrow[64];
#pragma unroll
        for (int i = 0; i < 64; i++) wrow[i] = w_qkv[t * 64 + i];
        const float bj = b_qkv[t];
        for (int l = 0; l < LTOK; l++) {
            float acc = bj;
#pragma unroll
            for (int i = 0; i < 64; i++) acc += sm_a[l * 64 + i] * wrow[i];
            sm_qkv[l * 192 + t] = acc;
        }
    }
    __syncthreads();

    // Phase 3: attention (one (head, l) per thread)
    {
        const int h = t / LTOK;
        const int l = t - h * LTOK;
        const float scale = 0.3535533905932738f;
        float sc[LTOK];
        float mx = -1e30f;
#pragma unroll
        for (int m = 0; m < LTOK; m++) {
            float s_ = 0.f;
#pragma unroll
            for (int d = 0; d < DHD; d++)
                s_ += sm_qkv[l * 192 + h * 8 + d] * sm_qkv[m * 192 + 64 + h * 8 + d];
            sc[m] = s_ * scale;
            mx = fmaxf(mx, sc[m]);
        }
        float denom = 0.f;
#pragma unroll
        for (int m = 0; m < LTOK; m++) { sc[m] = expf(sc[m] - mx); denom += sc[m]; }
        const float inv = 1.f / denom;
        float ov[DHD];
#pragma unroll
        for (int d = 0; d < DHD; d++) ov[d] = 0.f;
#pragma unroll
        for (int m = 0; m < LTOK; m++) {
            const float p_ = sc[m];
#pragma unroll
            for (int d = 0; d < DHD; d++)
                ov[d] += p_ * sm_qkv[m * 192 + 128 + h * 8 + d];
        }
#pragma unroll
        for (int d = 0; d < DHD; d++)
            sm_a[l * 64 + h * 8 + d] = ov[d] * inv;
    }
    __syncthreads();

    // Phase 4: output projection
    if (t < 64) {
        const float bj = b_out[t];
        for (int l = 0; l < LTOK; l++) {
            float acc = bj;
#pragma unroll
            for (int c = 0; c < 64; c++) acc += sm_a[l * 64 + c] * w_out[t * 64 + c];
            sm_k1[l * 64 + t] = acc;
        }
    }
    __syncthreads();

    // Phase 5: SE gate per window, write scaled weights to [win][ci][tap][co]
    for (int w_ = 0; w_ < WINS; w_++) {
        if (t < 64) {
            float pl = 0.f;
#pragma unroll
            for (int p = 0; p < 9; p++) pl += sm_k1[(w_ * 9 + p) * 64 + t];
            sm_pooled[t] = pl * (1.f / 9.f);
        }
        __syncthreads();
        if (t < 4) {
            float a = se_b1[w_ * 4 + t];
            for (int i = 0; i < 64; i++)
                a += sm_pooled[i] * se_w1[(w_ * 4 + t) * 64 + i];
            sm_h1[t] = fmaxf(a, 0.f);
        }
        __syncthreads();
        if (t < 64) {   // t = ci
            float z = se_b2[w_ * 64 + t];
#pragma unroll
            for (int r = 0; r < 4; r++) z += sm_h1[r] * se_w2[(w_ * 64 + t) * 4 + r];
            const float s_ = 1.f / (1.f + expf(-z));
#pragma unroll
            for (int p = 0; p < 9; p++)
                g_weights[((w_ * 64 + t) * 9 + p) * 64 + o] =
                    sm_k1[(w_ * 9 + p) * 64 + t] * s_;
        }
        __syncthreads();
    }
}

// ===========================================================================
// Kernel B: fused dynamic conv + LN + residual, FFMA2 (f32x2) datapath.
// Thread: 8 horizontal pixels x 16 output channels (co quarter q).
// Block: 128 threads -> tile 32 wide x 8 tall. Grid (64, 4, 8).
// LN reduced across the q-quad via shfl_xor.
// ===========================================================================
#define CI_CHUNK 8

__global__ void __launch_bounds__(128, 2) conv_ln(
    const float* __restrict__ x,
    const float* __restrict__ ln_w,
    const float* __restrict__ ln_b,
    float* __restrict__ out)
{
    __shared__ float xs[CI_CHUNK][10][36];     // halo tile per ci (34 used +2 pad)
    __shared__ float ws[CI_CHUNK][9][64];      // [ci][tap][co]
    __shared__ float lnw[64], lnb[64];

    const int b   = blockIdx.z;
    const int w_  = blockIdx.y;
    const int tb  = blockIdx.x;                // 16 y-tiles x 4 x-tiles
    const int ty0 = (tb >> 2) << 3;            // 0..120
    const int tx0 = (tb & 3) << 5;             // 0,32,64,96
    const int base_y = (w_ >> 1) << 7;
    const int base_x = (w_ & 1) << 7;

    const int t   = threadIdx.x;
    const int q   = t & 3;                     // co quarter: co = q*16 .. q*16+15
    const int xsI = (t >> 2) & 3;              // x strip
    const int y   = t >> 4;                    // 0..7
    const int xb  = xsI << 3;                  // strip start col in tile

    if (t < 64) { lnw[t] = ln_w[t]; lnb[t] = ln_b[t]; }

    // acc[p*8+cp] = f32x2 pair for pixel p, channels (16q+2cp, 16q+2cp+1)
    ull acc[64];
#pragma unroll
    for (int i = 0; i < 64; i++) acc[i] = 0ULL;

    for (int c0 = 0; c0 < 64; c0 += CI_CHUNK) {
        __syncthreads();   // previous chunk consumed (covers lnw init too)

        // ---- stage x halo tile (zero outside this 128x128 window)
        for (int idx = t; idx < CI_CHUNK * 340; idx += 128) {
            int ci = idx / 340; int rr = idx - ci * 340;
            int r = rr / 34, c = rr - 34 * r;
            int ly = ty0 + r - 1, lx = tx0 + c - 1;
            float v = 0.f;
            if ((unsigned)ly < 128u && (unsigned)lx < 128u)
                v = x[((b * 64 + c0 + ci) * 256 + (base_y + ly)) * 256 + (base_x + lx)];
            xs[ci][r][c] = v;
        }
        // ---- stage weight chunk: 8*9*64 floats = 1152 float4
        {
            const float4* gw = (const float4*)&g_weights[((w_ * 64 + c0) * 9) * 64];
            float4* wd = (float4*)ws;
            for (int idx = t; idx < CI_CHUNK * 9 * 16; idx += 128)
                wd[idx] = gw[idx];
        }
        __syncthreads();

#pragma unroll 1
        for (int ci = 0; ci < CI_CHUNK; ci++) {
#pragma unroll
            for (int ky = 0; ky < 3; ky++) {
                // duplicate the 10 x values this thread needs for this row
                ull xd[10];
                const float* xrow = &xs[ci][y + ky][xb];
#pragma unroll
                for (int j = 0; j < 10; j++) DUP2(xd[j], xrow[j]);
#pragma unroll
                for (int kx = 0; kx < 3; kx++) {
                    // 8 x LDS.64 weight pairs for this thread's 16 channels;
                    // start index staggered by 2q to avoid bank aliasing
                    const ull* wrow = (const ull*)&ws[ci][ky * 3 + kx][q << 4];
                    ull w2[8];
#pragma unroll
                    for (int ii = 0; ii < 8; ii++) {
                        int i = (ii + 2 * q) & 7;
                        w2[i] = wrow[i];
                    }
#pragma unroll
                    for (int p = 0; p < 8; p++) {
                        const ull xv = xd[p + kx];
#pragma unroll
                        for (int cp = 0; cp < 8; cp++)
                            FMA2(acc[p * 8 + cp], w2[cp], xv);
                    }
                }
            }
        }
    }

    // ---- LayerNorm over 64 channels: two-pass, reduced across the q-quad
    float mu[8], inv[8];
#pragma unroll
    for (int p = 0; p < 8; p++) {
        float s = 0.f;
#pragma unroll
        for (int cp = 0; cp < 8; cp++) {
            unsigned lo, hi; UNPACK2(lo, hi, acc[p * 8 + cp]);
            s += __uint_as_float(lo) + __uint_as_float(hi);
        }
        s += __shfl_xor_sync(0xffffffffu, s, 1);
        s += __shfl_xor_sync(0xffffffffu, s, 2);
        mu[p] = s * (1.f / 64.f);
    }
#pragma unroll
    for (int p = 0; p < 8; p++) {
        float ss = 0.f;
        const float m = mu[p];
#pragma unroll
        for (int cp = 0; cp < 8; cp++) {
            unsigned lo, hi; UNPACK2(lo, hi, acc[p * 8 + cp]);
            float a = __uint_as_float(lo) - m, c = __uint_as_float(hi) - m;
            ss += a * a + c * c;
        }
        ss += __shfl_xor_sync(0xffffffffu, ss, 1);
        ss += __shfl_xor_sync(0xffffffffu, ss, 2);
        inv[p] = rsqrtf(ss * (1.f / 64.f) + 1e-5f);
    }

    // ---- residual + store (8 consecutive floats per co -> 2x float4)
    const int gy  = base_y + ty0 + y;
    const int gx0 = base_x + tx0 + xb;
#pragma unroll
    for (int j = 0; j < 16; j++) {
        const int co = (q << 4) + j;
        const float g = lnw[co], bb_ = lnb[co];
        const float* xp = &x[((b * 64 + co) * 256 + gy) * 256 + gx0];
        float4 r0 = ((const float4*)xp)[0];
        float4 r1 = ((const float4*)xp)[1];
        float v[8];
#pragma unroll
        for (int cp = 0; cp < 8; cp++) {
            unsigned lo, hi; UNPACK2(lo, hi, acc[(cp) * 8 + (j >> 1)]);
            v[cp] = (j & 1) ? __uint_as_float(hi) : __uint_as_float(lo);
        }
#pragma unroll
        for (int p = 0; p < 8; p++)
            v[p] = (v[p] - mu[p]) * inv[p] * g + bb_;
        float4 o0 = make_float4(r0.x + v[0], r0.y + v[1], r0.z + v[2], r0.w + v[3]);
        float4 o1 = make_float4(r1.x + v[4], r1.y + v[5], r1.z + v[6], r1.w + v[7]);
        float* op = &out[((b * 64 + co) * 256 + gy) * 256 + gx0];
        ((float4*)op)[0] = o0;
        ((float4*)op)[1] = o1;
    }
}

// ===========================================================================
extern "C" void kernel_launch(void* const* d_in, const int* in_sizes, int n_in,
                              void* d_out, int out_size)
{
    const float* x      = (const float*)d_in[0];
    const float* conv_w = (const float*)d_in[1];
    const float* w_qkv  = (const float*)d_in[2];
    const float* b_qkv  = (const float*)d_in[3];
    const float* w_out  = (const float*)d_in[4];
    const float* b_out  = (const float*)d_in[5];
    const float* se_w1  = (const float*)d_in[6];
    const float* se_b1  = (const float*)d_in[7];
    const float* se_w2  = (const float*)d_in[8];
    const float* se_b2  = (const float*)d_in[9];
    const float* ln_w   = (const float*)d_in[10];
    const float* ln_b   = (const float*)d_in[11];
    float* out = (float*)d_out;

    gen_kernels<<<64, 288>>>(conv_w, w_qkv, b_qkv, w_out, b_out,
                             se_w1, se_b1, se_w2, se_b2);
    conv_ln<<<dim3(64, 4, 8), 128>>>(x, ln_w, ln_b, out);
}

// round 5
// speedup vs baseline: 9.8560x; 9.8560x over previous
#include <cuda_runtime.h>
#include <math.h>

#define DIMC   64
#define WINS   4
#define LTOK   36
#define DHD    8

typedef unsigned long long ull;

// Scratch: dynamic conv weights, layout [win][ci][tap][co]
__device__ __align__(16) float g_weights[WINS * 64 * 9 * 64];

#define FMA2(acc, a, b) \
    asm("fma.rn.f32x2 %0, %1, %2, %0;" : "+l"(acc) : "l"(a), "l"(b))
#define DUP2(d, f) \
    asm("mov.b64 %0, {%1, %1};" : "=l"(d) : "r"(__float_as_uint(f)))
#define UNPACK2(lo, hi, v) \
    asm("mov.b64 {%0, %1}, %2;" : "=r"(lo), "=r"(hi) : "l"(v))

// ===========================================================================
// Kernel A: build dynamic conv kernels (attention + SE). One block per o.
// ===========================================================================
__global__ void __launch_bounds__(288) gen_kernels(
    const float* __restrict__ conv_w,
    const float* __restrict__ w_qkv,
    const float* __restrict__ b_qkv,
    const float* __restrict__ w_out,
    const float* __restrict__ b_out,
    const float* __restrict__ se_w1,
    const float* __restrict__ se_b1,
    const float* __restrict__ se_w2,
    const float* __restrict__ se_b2)
{
    __shared__ float sm_a[LTOK * 64];
    __shared__ float sm_qkv[LTOK * 192];
    __shared__ float sm_k1[LTOK * 64];
    __shared__ float sm_pooled[64];
    __shared__ float sm_h1[4];

    const int o = blockIdx.x;
    const int t = threadIdx.x;

    for (int idx = t; idx < LTOK * 64; idx += 288) {
        int l = idx >> 6, i = idx & 63;
        int w_ = l / 9, p = l - w_ * 9;
        sm_a[idx] = conv_w[(((w_ * 64 + o) * 64 + i) * 9) + p];
    }
    __syncthreads();

    if (t < 192) {
        float wrow[64];
#pragma unroll
        for (int i = 0; i < 64; i++) wrow[i] = w_qkv[t * 64 + i];
        const float bj = b_qkv[t];
        for (int l = 0; l < LTOK; l++) {
            float acc = bj;
#pragma unroll
            for (int i = 0; i < 64; i++) acc += sm_a[l * 64 + i] * wrow[i];
            sm_qkv[l * 192 + t] = acc;
        }
    }
    __syncthreads();

    {
        const int h = t / LTOK;
        const int l = t - h * LTOK;
        const float scale = 0.3535533905932738f;
        float sc[LTOK];
        float mx = -1e30f;
#pragma unroll
        for (int m = 0; m < LTOK; m++) {
            float s_ = 0.f;
#pragma unroll
            for (int d = 0; d < DHD; d++)
                s_ += sm_qkv[l * 192 + h * 8 + d] * sm_qkv[m * 192 + 64 + h * 8 + d];
            sc[m] = s_ * scale;
            mx = fmaxf(mx, sc[m]);
        }
        float denom = 0.f;
#pragma unroll
        for (int m = 0; m < LTOK; m++) { sc[m] = expf(sc[m] - mx); denom += sc[m]; }
        const float inv = 1.f / denom;
        float ov[DHD];
#pragma unroll
        for (int d = 0; d < DHD; d++) ov[d] = 0.f;
#pragma unroll
        for (int m = 0; m < LTOK; m++) {
            const float p_ = sc[m];
#pragma unroll
            for (int d = 0; d < DHD; d++)
                ov[d] += p_ * sm_qkv[m * 192 + 128 + h * 8 + d];
        }
#pragma unroll
        for (int d = 0; d < DHD; d++)
            sm_a[l * 64 + h * 8 + d] = ov[d] * inv;
    }
    __syncthreads();

    if (t < 64) {
        const float bj = b_out[t];
        for (int l = 0; l < LTOK; l++) {
            float acc = bj;
#pragma unroll
            for (int c = 0; c < 64; c++) acc += sm_a[l * 64 + c] * w_out[t * 64 + c];
            sm_k1[l * 64 + t] = acc;
        }
    }
    __syncthreads();

    for (int w_ = 0; w_ < WINS; w_++) {
        if (t < 64) {
            float pl = 0.f;
#pragma unroll
            for (int p = 0; p < 9; p++) pl += sm_k1[(w_ * 9 + p) * 64 + t];
            sm_pooled[t] = pl * (1.f / 9.f);
        }
        __syncthreads();
        if (t < 4) {
            float a = se_b1[w_ * 4 + t];
            for (int i = 0; i < 64; i++)
                a += sm_pooled[i] * se_w1[(w_ * 4 + t) * 64 + i];
            sm_h1[t] = fmaxf(a, 0.f);
        }
        __syncthreads();
        if (t < 64) {   // t = ci
            float z = se_b2[w_ * 64 + t];
#pragma unroll
            for (int r = 0; r < 4; r++) z += sm_h1[r] * se_w2[(w_ * 64 + t) * 4 + r];
            const float s_ = 1.f / (1.f + expf(-z));
#pragma unroll
            for (int p = 0; p < 9; p++)
                g_weights[((w_ * 64 + t) * 9 + p) * 64 + o] =
                    sm_k1[(w_ * 9 + p) * 64 + t] * s_;
        }
        __syncthreads();
    }
}

// ===========================================================================
// Kernel B: fused conv + LN + residual, f32x2 datapath, spill-safe budget.
// Thread = 8 horizontal pixels x 8 output channels. Block 256 = tile 32x8.
// Lane layout: lane = strip*8 + co_g  (strip 0..3, co_g 0..7); warp = row y.
// LN reduced over co_g lanes via shfl_xor 1,2,4.
// ===========================================================================
#define CI_CHUNK 8
// swizzled float offset of an 8-channel chunk within a 68-float tap row
__device__ __forceinline__ int wswz(int co_g) { return co_g * 8 + ((co_g >= 4) ? 4 : 0); }

__global__ void __launch_bounds__(256, 2) conv_ln(
    const float* __restrict__ x,
    const float* __restrict__ ln_w,
    const float* __restrict__ ln_b,
    float* __restrict__ out)
{
    __shared__ float xs[CI_CHUNK][10][36];     // [ci][row][col], 34 cols used
    __shared__ float ws[CI_CHUNK][9][68];      // swizzled: chunk co_g at wswz(co_g)
    __shared__ float lnw[64], lnb[64];

    const int b   = blockIdx.z;
    const int w_  = blockIdx.y;
    const int tb  = blockIdx.x;                // 16 y-tiles x 4 x-tiles
    const int ty0 = (tb >> 2) << 3;
    const int tx0 = (tb & 3) << 5;
    const int base_y = (w_ >> 1) << 7;
    const int base_x = (w_ & 1) << 7;

    const int t    = threadIdx.x;
    const int y    = t >> 5;                   // warp = tile row
    const int lane = t & 31;
    const int strip = lane >> 3;               // 8-pixel strip
    const int co_g  = lane & 7;                // channel octet
    const int xb    = strip << 3;
    const int wsoff = wswz(co_g);

    if (t < 64) { lnw[t] = ln_w[t]; lnb[t] = ln_b[t]; }

    // acc[p*4+c2]: f32x2 for pixel p, channels (co_g*8 + 2*c2, +1)
    ull acc[32];
#pragma unroll
    for (int i = 0; i < 32; i++) acc[i] = 0ULL;

    for (int c0 = 0; c0 < 64; c0 += CI_CHUNK) {
        __syncthreads();

        // stage x halo tiles (zero outside the 128x128 window)
        for (int idx = t; idx < CI_CHUNK * 340; idx += 256) {
            int ci = idx / 340; int rr = idx - ci * 340;
            int r = rr / 34, c = rr - 34 * r;
            int ly = ty0 + r - 1, lx = tx0 + c - 1;
            float v = 0.f;
            if ((unsigned)ly < 128u && (unsigned)lx < 128u)
                v = x[((b * 64 + c0 + ci) * 256 + (base_y + ly)) * 256 + (base_x + lx)];
            xs[ci][r][c] = v;
        }
        // stage weights with bank swizzle: 8 ci x 9 taps x 16 float4
        {
            const float4* gw = (const float4*)&g_weights[((w_ * 64 + c0) * 9) * 64];
            for (int idx = t; idx < CI_CHUNK * 9 * 16; idx += 256) {
                int ci = idx / 144; int rr = idx - ci * 144;
                int tap = rr >> 4, c4 = rr & 15;
                int cg = c4 >> 1;
                int dst = cg * 8 + ((cg >= 4) ? 4 : 0) + ((c4 & 1) << 2);
                *(float4*)&ws[ci][tap][dst] = gw[idx];
            }
        }
        __syncthreads();

#pragma unroll 1
        for (int ci = 0; ci < CI_CHUNK; ci++) {
#pragma unroll
            for (int ky = 0; ky < 3; ky++) {
                ull xd[10];
                const float* xrow = &xs[ci][y + ky][xb];
#pragma unroll
                for (int j = 0; j < 10; j++) DUP2(xd[j], xrow[j]);
#pragma unroll
                for (int kx = 0; kx < 3; kx++) {
                    const ull* wp = (const ull*)&ws[ci][ky * 3 + kx][wsoff];
                    ull w0 = wp[0], w1 = wp[1], w2 = wp[2], w3 = wp[3];
#pragma unroll
                    for (int p = 0; p < 8; p++) {
                        const ull xv = xd[p + kx];
                        FMA2(acc[p * 4 + 0], w0, xv);
                        FMA2(acc[p * 4 + 1], w1, xv);
                        FMA2(acc[p * 4 + 2], w2, xv);
                        FMA2(acc[p * 4 + 3], w3, xv);
                    }
                }
            }
        }
    }

    // ---- LayerNorm over 64 channels: reduce 8 local + shfl over co_g lanes
    float mu[8], inv[8];
#pragma unroll
    for (int p = 0; p < 8; p++) {
        float s = 0.f;
#pragma unroll
        for (int c2 = 0; c2 < 4; c2++) {
            unsigned lo, hi; UNPACK2(lo, hi, acc[p * 4 + c2]);
            s += __uint_as_float(lo) + __uint_as_float(hi);
        }
        s += __shfl_xor_sync(0xffffffffu, s, 1);
        s += __shfl_xor_sync(0xffffffffu, s, 2);
        s += __shfl_xor_sync(0xffffffffu, s, 4);
        mu[p] = s * (1.f / 64.f);
    }
#pragma unroll
    for (int p = 0; p < 8; p++) {
        float ss = 0.f;
        const float m = mu[p];
#pragma unroll
        for (int c2 = 0; c2 < 4; c2++) {
            unsigned lo, hi; UNPACK2(lo, hi, acc[p * 4 + c2]);
            float a = __uint_as_float(lo) - m, c = __uint_as_float(hi) - m;
            ss += a * a + c * c;
        }
        ss += __shfl_xor_sync(0xffffffffu, ss, 1);
        ss += __shfl_xor_sync(0xffffffffu, ss, 2);
        ss += __shfl_xor_sync(0xffffffffu, ss, 4);
        inv[p] = rsqrtf(ss * (1.f / 64.f) + 1e-5f);
    }

    // ---- residual + store: 8 channels x 8 consecutive pixels (2x float4 each)
    const int gy  = base_y + ty0 + y;
    const int gx0 = base_x + tx0 + xb;
#pragma unroll
    for (int k = 0; k < 8; k++) {
        const int co = (co_g << 3) + k;
        const float g = lnw[co], bb_ = lnb[co];
        const long ofs = ((long)(b * 64 + co) * 256 + gy) * 256 + gx0;
        float4 r0 = ((const float4*)(x + ofs))[0];
        float4 r1 = ((const float4*)(x + ofs))[1];
        float v[8];
#pragma unroll
        for (int p = 0; p < 8; p++) {
            unsigned lo, hi; UNPACK2(lo, hi, acc[p * 4 + (k >> 1)]);
            float a = (k & 1) ? __uint_as_float(hi) : __uint_as_float(lo);
            v[p] = (a - mu[p]) * inv[p] * g + bb_;
        }
        float4 o0 = make_float4(r0.x + v[0], r0.y + v[1], r0.z + v[2], r0.w + v[3]);
        float4 o1 = make_float4(r1.x + v[4], r1.y + v[5], r1.z + v[6], r1.w + v[7]);
        ((float4*)(out + ofs))[0] = o0;
        ((float4*)(out + ofs))[1] = o1;
    }
}

// ===========================================================================
extern "C" void kernel_launch(void* const* d_in, const int* in_sizes, int n_in,
                              void* d_out, int out_size)
{
    const float* x      = (const float*)d_in[0];
    const float* conv_w = (const float*)d_in[1];
    const float* w_qkv  = (const float*)d_in[2];
    const float* b_qkv  = (const float*)d_in[3];
    const float* w_out  = (const float*)d_in[4];
    const float* b_out  = (const float*)d_in[5];
    const float* se_w1  = (const float*)d_in[6];
    const float* se_b1  = (const float*)d_in[7];
    const float* se_w2  = (const float*)d_in[8];
    const float* se_b2  = (const float*)d_in[9];
    const float* ln_w   = (const float*)d_in[10];
    const float* ln_b   = (const float*)d_in[11];
    float* out = (float*)d_out;

    gen_kernels<<<64, 288>>>(conv_w, w_qkv, b_qkv, w_out, b_out,
                             se_w1, se_b1, se_w2, se_b2);
    conv_ln<<<dim3(64, 4, 8), 256>>>(x, ln_w, ln_b, out);
}

// round 6
// speedup vs baseline: 9.9057x; 1.0050x over previous
#include <cuda_runtime.h>
#include <math.h>

#define DIMC   64
#define WINS   4
#define LTOK   36
#define DHD    8

typedef unsigned long long ull;

// Scratch: dynamic conv weights, layout [win][ci][tap][co]
__device__ __align__(16) float g_weights[WINS * 64 * 9 * 64];

#define FMA2(acc, a, b) \
    asm("fma.rn.f32x2 %0, %1, %2, %0;" : "+l"(acc) : "l"(a), "l"(b))
#define DUP2(d, f) \
    asm("mov.b64 %0, {%1, %1};" : "=l"(d) : "r"(__float_as_uint(f)))
#define UNPACK2(lo, hi, v) \
    asm("mov.b64 {%0, %1}, %2;" : "=r"(lo), "=r"(hi) : "l"(v))

// ===========================================================================
// Kernel A: build dynamic conv kernels (attention + SE). One block per o.
// ===========================================================================
__global__ void __launch_bounds__(288) gen_kernels(
    const float* __restrict__ conv_w,
    const float* __restrict__ w_qkv,
    const float* __restrict__ b_qkv,
    const float* __restrict__ w_out,
    const float* __restrict__ b_out,
    const float* __restrict__ se_w1,
    const float* __restrict__ se_b1,
    const float* __restrict__ se_w2,
    const float* __restrict__ se_b2)
{
    __shared__ float sm_a[LTOK * 64];
    __shared__ float sm_qkv[LTOK * 192];
    __shared__ float sm_k1[LTOK * 64];
    __shared__ float sm_pooled[64];
    __shared__ float sm_h1[4];

    const int o = blockIdx.x;
    const int t = threadIdx.x;

    for (int idx = t; idx < LTOK * 64; idx += 288) {
        int l = idx >> 6, i = idx & 63;
        int w_ = l / 9, p = l - w_ * 9;
        sm_a[idx] = conv_w[(((w_ * 64 + o) * 64 + i) * 9) + p];
    }
    __syncthreads();

    if (t < 192) {
        float wrow[64];
#pragma unroll
        for (int i = 0; i < 64; i++) wrow[i] = w_qkv[t * 64 + i];
        const float bj = b_qkv[t];
        for (int l = 0; l < LTOK; l++) {
            float acc = bj;
#pragma unroll
            for (int i = 0; i < 64; i++) acc += sm_a[l * 64 + i] * wrow[i];
            sm_qkv[l * 192 + t] = acc;
        }
    }
    __syncthreads();

    {
        const int h = t / LTOK;
        const int l = t - h * LTOK;
        const float scale = 0.3535533905932738f;
        float sc[LTOK];
        float mx = -1e30f;
#pragma unroll
        for (int m = 0; m < LTOK; m++) {
            float s_ = 0.f;
#pragma unroll
            for (int d = 0; d < DHD; d++)
                s_ += sm_qkv[l * 192 + h * 8 + d] * sm_qkv[m * 192 + 64 + h * 8 + d];
            sc[m] = s_ * scale;
            mx = fmaxf(mx, sc[m]);
        }
        float denom = 0.f;
#pragma unroll
        for (int m = 0; m < LTOK; m++) { sc[m] = expf(sc[m] - mx); denom += sc[m]; }
        const float inv = 1.f / denom;
        float ov[DHD];
#pragma unroll
        for (int d = 0; d < DHD; d++) ov[d] = 0.f;
#pragma unroll
        for (int m = 0; m < LTOK; m++) {
            const float p_ = sc[m];
#pragma unroll
            for (int d = 0; d < DHD; d++)
                ov[d] += p_ * sm_qkv[m * 192 + 128 + h * 8 + d];
        }
#pragma unroll
        for (int d = 0; d < DHD; d++)
            sm_a[l * 64 + h * 8 + d] = ov[d] * inv;
    }
    __syncthreads();

    if (t < 64) {
        const float bj = b_out[t];
        for (int l = 0; l < LTOK; l++) {
            float acc = bj;
#pragma unroll
            for (int c = 0; c < 64; c++) acc += sm_a[l * 64 + c] * w_out[t * 64 + c];
            sm_k1[l * 64 + t] = acc;
        }
    }
    __syncthreads();

    for (int w_ = 0; w_ < WINS; w_++) {
        if (t < 64) {
            float pl = 0.f;
#pragma unroll
            for (int p = 0; p < 9; p++) pl += sm_k1[(w_ * 9 + p) * 64 + t];
            sm_pooled[t] = pl * (1.f / 9.f);
        }
        __syncthreads();
        if (t < 4) {
            float a = se_b1[w_ * 4 + t];
            for (int i = 0; i < 64; i++)
                a += sm_pooled[i] * se_w1[(w_ * 4 + t) * 64 + i];
            sm_h1[t] = fmaxf(a, 0.f);
        }
        __syncthreads();
        if (t < 64) {   // t = ci
            float z = se_b2[w_ * 64 + t];
#pragma unroll
            for (int r = 0; r < 4; r++) z += sm_h1[r] * se_w2[(w_ * 64 + t) * 4 + r];
            const float s_ = 1.f / (1.f + expf(-z));
#pragma unroll
            for (int p = 0; p < 9; p++)
                g_weights[((w_ * 64 + t) * 9 + p) * 64 + o] =
                    sm_k1[(w_ * 9 + p) * 64 + t] * s_;
        }
        __syncthreads();
    }
}

// ===========================================================================
// Kernel B: fused conv + LN + residual, f32x2 datapath, spill-safe budget.
// Thread = 8 horizontal pixels x 8 output channels. Block 256 = tile 32x8.
// Lane layout: lane = strip*8 + co_g  (strip 0..3, co_g 0..7); warp = row y.
// LN reduced over co_g lanes via shfl_xor 1,2,4.
// ===========================================================================
#define CI_CHUNK 8
// swizzled float offset of an 8-channel chunk within a 68-float tap row
__device__ __forceinline__ int wswz(int co_g) { return co_g * 8 + ((co_g >= 4) ? 4 : 0); }

__global__ void __launch_bounds__(256, 2) conv_ln(
    const float* __restrict__ x,
    const float* __restrict__ ln_w,
    const float* __restrict__ ln_b,
    float* __restrict__ out)
{
    __shared__ float xs[CI_CHUNK][10][36];     // [ci][row][col], 34 cols used
    __shared__ float ws[CI_CHUNK][9][68];      // swizzled: chunk co_g at wswz(co_g)
    __shared__ float lnw[64], lnb[64];

    const int b   = blockIdx.z;
    const int w_  = blockIdx.y;
    const int tb  = blockIdx.x;                // 16 y-tiles x 4 x-tiles
    const int ty0 = (tb >> 2) << 3;
    const int tx0 = (tb & 3) << 5;
    const int base_y = (w_ >> 1) << 7;
    const int base_x = (w_ & 1) << 7;

    const int t    = threadIdx.x;
    const int y    = t >> 5;                   // warp = tile row
    const int lane = t & 31;
    const int strip = lane >> 3;               // 8-pixel strip
    const int co_g  = lane & 7;                // channel octet
    const int xb    = strip << 3;
    const int wsoff = wswz(co_g);

    if (t < 64) { lnw[t] = ln_w[t]; lnb[t] = ln_b[t]; }

    // acc[p*4+c2]: f32x2 for pixel p, channels (co_g*8 + 2*c2, +1)
    ull acc[32];
#pragma unroll
    for (int i = 0; i < 32; i++) acc[i] = 0ULL;

    for (int c0 = 0; c0 < 64; c0 += CI_CHUNK) {
        __syncthreads();

        // stage x halo tiles (zero outside the 128x128 window)
        for (int idx = t; idx < CI_CHUNK * 340; idx += 256) {
            int ci = idx / 340; int rr = idx - ci * 340;
            int r = rr / 34, c = rr - 34 * r;
            int ly = ty0 + r - 1, lx = tx0 + c - 1;
            float v = 0.f;
            if ((unsigned)ly < 128u && (unsigned)lx < 128u)
                v = x[((b * 64 + c0 + ci) * 256 + (base_y + ly)) * 256 + (base_x + lx)];
            xs[ci][r][c] = v;
        }
        // stage weights with bank swizzle: 8 ci x 9 taps x 16 float4
        {
            const float4* gw = (const float4*)&g_weights[((w_ * 64 + c0) * 9) * 64];
            for (int idx = t; idx < CI_CHUNK * 9 * 16; idx += 256) {
                int ci = idx / 144; int rr = idx - ci * 144;
                int tap = rr >> 4, c4 = rr & 15;
                int cg = c4 >> 1;
                int dst = cg * 8 + ((cg >= 4) ? 4 : 0) + ((c4 & 1) << 2);
                *(float4*)&ws[ci][tap][dst] = gw[idx];
            }
        }
        __syncthreads();

#pragma unroll 1
        for (int ci = 0; ci < CI_CHUNK; ci++) {
#pragma unroll
            for (int ky = 0; ky < 3; ky++) {
                ull xd[10];
                const float* xrow = &xs[ci][y + ky][xb];
#pragma unroll
                for (int j = 0; j < 10; j++) DUP2(xd[j], xrow[j]);
#pragma unroll
                for (int kx = 0; kx < 3; kx++) {
                    const ull* wp = (const ull*)&ws[ci][ky * 3 + kx][wsoff];
                    ull w0 = wp[0], w1 = wp[1], w2 = wp[2], w3 = wp[3];
#pragma unroll
                    for (int p = 0; p < 8; p++) {
                        const ull xv = xd[p + kx];
                        FMA2(acc[p * 4 + 0], w0, xv);
                        FMA2(acc[p * 4 + 1], w1, xv);
                        FMA2(acc[p * 4 + 2], w2, xv);
                        FMA2(acc[p * 4 + 3], w3, xv);
                    }
                }
            }
        }
    }

    // ---- LayerNorm over 64 channels: reduce 8 local + shfl over co_g lanes
    float mu[8], inv[8];
#pragma unroll
    for (int p = 0; p < 8; p++) {
        float s = 0.f;
#pragma unroll
        for (int c2 = 0; c2 < 4; c2++) {
            unsigned lo, hi; UNPACK2(lo, hi, acc[p * 4 + c2]);
            s += __uint_as_float(lo) + __uint_as_float(hi);
        }
        s += __shfl_xor_sync(0xffffffffu, s, 1);
        s += __shfl_xor_sync(0xffffffffu, s, 2);
        s += __shfl_xor_sync(0xffffffffu, s, 4);
        mu[p] = s * (1.f / 64.f);
    }
#pragma unroll
    for (int p = 0; p < 8; p++) {
        float ss = 0.f;
        const float m = mu[p];
#pragma unroll
        for (int c2 = 0; c2 < 4; c2++) {
            unsigned lo, hi; UNPACK2(lo, hi, acc[p * 4 + c2]);
            float a = __uint_as_float(lo) - m, c = __uint_as_float(hi) - m;
            ss += a * a + c * c;
        }
        ss += __shfl_xor_sync(0xffffffffu, ss, 1);
        ss += __shfl_xor_sync(0xffffffffu, ss, 2);
        ss += __shfl_xor_sync(0xffffffffu, ss, 4);
        inv[p] = rsqrtf(ss * (1.f / 64.f) + 1e-5f);
    }

    // ---- residual + store: 8 channels x 8 consecutive pixels (2x float4 each)
    const int gy  = base_y + ty0 + y;
    const int gx0 = base_x + tx0 + xb;
#pragma unroll
    for (int k = 0; k < 8; k++) {
        const int co = (co_g << 3) + k;
        const float g = lnw[co], bb_ = lnb[co];
        const long ofs = ((long)(b * 64 + co) * 256 + gy) * 256 + gx0;
        float4 r0 = ((const float4*)(x + ofs))[0];
        float4 r1 = ((const float4*)(x + ofs))[1];
        float v[8];
#pragma unroll
        for (int p = 0; p < 8; p++) {
            unsigned lo, hi; UNPACK2(lo, hi, acc[p * 4 + (k >> 1)]);
            float a = (k & 1) ? __uint_as_float(hi) : __uint_as_float(lo);
            v[p] = (a - mu[p]) * inv[p] * g + bb_;
        }
        float4 o0 = make_float4(r0.x + v[0], r0.y + v[1], r0.z + v[2], r0.w + v[3]);
        float4 o1 = make_float4(r1.x + v[4], r1.y + v[5], r1.z + v[6], r1.w + v[7]);
        ((float4*)(out + ofs))[0] = o0;
        ((float4*)(out + ofs))[1] = o1;
    }
}

// ===========================================================================
extern "C" void kernel_launch(void* const* d_in, const int* in_sizes, int n_in,
                              void* d_out, int out_size)
{
    const float* x      = (const float*)d_in[0];
    const float* conv_w = (const float*)d_in[1];
    const float* w_qkv  = (const float*)d_in[2];
    const float* b_qkv  = (const float*)d_in[3];
    const float* w_out  = (const float*)d_in[4];
    const float* b_out  = (const float*)d_in[5];
    const float* se_w1  = (const float*)d_in[6];
    const float* se_b1  = (const float*)d_in[7];
    const float* se_w2  = (const float*)d_in[8];
    const float* se_b2  = (const float*)d_in[9];
    const float* ln_w   = (const float*)d_in[10];
    const float* ln_b   = (const float*)d_in[11];
    float* out = (float*)d_out;

    gen_kernels<<<64, 288>>>(conv_w, w_qkv, b_qkv, w_out, b_out,
                             se_w1, se_b1, se_w2, se_b2);
    conv_ln<<<dim3(64, 4, 8), 256>>>(x, ln_w, ln_b, out);
}

// round 8
// speedup vs baseline: 15.9094x; 1.6061x over previous
#include <cuda_runtime.h>
#include <cuda_bf16.h>
#include <math.h>
#include <cstdint>

#define WINS 4
#define LTOK 36
#define DHD  8

// Weights, mma-B-fragment interleaved: [win][chunk4][tap9][hl2][co64][16] bf16
__device__ __align__(16) __nv_bfloat16 g_wB[4 * 4 * 9 * 2 * 64 * 16];
// X converted: [hl][b][wx2][chunk4][gy256][px132][ci16] bf16 (px slot 0 and 129+ are zero)
__device__ __align__(16) __nv_bfloat16 g_xbf[2ULL * 8 * 2 * 4 * 256 * 132 * 16];

__device__ __forceinline__ uint32_t smem_u32(const void* p) {
    uint32_t a;
    asm("{ .reg .u64 t; cvta.to.shared.u64 t, %1; cvt.u32.u64 %0, t; }" : "=r"(a) : "l"(p));
    return a;
}

__device__ __forceinline__ void ldmx4(uint32_t* r, uint32_t addr) {
    asm volatile("ldmatrix.sync.aligned.m8n8.x4.shared.b16 {%0,%1,%2,%3}, [%4];"
        : "=r"(r[0]), "=r"(r[1]), "=r"(r[2]), "=r"(r[3]) : "r"(addr));
}

__device__ __forceinline__ void mma16816(float* d, const uint32_t* a, uint2 b) {
    asm volatile("mma.sync.aligned.m16n8k16.row.col.f32.bf16.bf16.f32 "
        "{%0,%1,%2,%3}, {%4,%5,%6,%7}, {%8,%9}, {%0,%1,%2,%3};"
        : "+f"(d[0]), "+f"(d[1]), "+f"(d[2]), "+f"(d[3])
        : "r"(a[0]), "r"(a[1]), "r"(a[2]), "r"(a[3]), "r"(b.x), "r"(b.y));
}

// ===========================================================================
// Kernel P: convert x -> bf16 hi/lo in mma-friendly layout with px halo baked.
// Block per (4 rows, wx*chunk, b). 256 threads.
// ===========================================================================
__global__ void __launch_bounds__(256) prep_x(const float* __restrict__ x)
{
    __shared__ __nv_bfloat16 xs[2][4 * 132 * 16];
    const int b  = blockIdx.z;
    const int wx = blockIdx.y >> 2;
    const int c  = blockIdx.y & 3;
    const int y0 = blockIdx.x << 2;
    const int t  = threadIdx.x;

    for (int idx = t; idx < 4 * 132 * 16; idx += 256) {
        int px = idx % 132;
        int rest = idx / 132;
        int ci = rest & 15;
        int y_l = rest >> 4;
        float v = 0.f;
        if (px >= 1 && px <= 128)
            v = x[(((size_t)(b * 64 + c * 16 + ci)) * 256 + (y0 + y_l)) * 256
                  + wx * 128 + px - 1];
        __nv_bfloat16 h = __float2bfloat16(v);
        __nv_bfloat16 l = __float2bfloat16(v - __bfloat162float(h));
        xs[0][(y_l * 132 + px) * 16 + ci] = h;
        xs[1][(y_l * 132 + px) * 16 + ci] = l;
    }
    __syncthreads();

    // coalesced 16B writes: per (hl, row): 264 uint4
    for (int idx = t; idx < 2 * 4 * 264; idx += 256) {
        int hl = idx / 1056;
        int rr = idx - hl * 1056;
        int y_l = rr / 264;
        int k = rr - y_l * 264;
        size_t rowbase = ((((((size_t)hl * 8 + b) * 2 + wx) * 4 + c) * 256
                          + (size_t)(y0 + y_l))) * 264;
        ((uint4*)g_xbf)[rowbase + k] = ((const uint4*)xs)[(hl * 4 + y_l) * 264 + k];
    }
}

// ===========================================================================
// Kernel A: attention + SE -> bf16 hi/lo weights in B-fragment interleave.
// One block per o (= co), 288 threads.
// ===========================================================================
__global__ void __launch_bounds__(288) gen_kernels(
    const float* __restrict__ conv_w, const float* __restrict__ w_qkv,
    const float* __restrict__ b_qkv,  const float* __restrict__ w_out,
    const float* __restrict__ b_out,  const float* __restrict__ se_w1,
    const float* __restrict__ se_b1,  const float* __restrict__ se_w2,
    const float* __restrict__ se_b2)
{
    __shared__ float sm_a[LTOK * 64];
    __shared__ float sm_qkv[LTOK * 192];
    __shared__ float sm_k1[LTOK * 64];
    __shared__ float sm_pooled[64];
    __shared__ float sm_h1[4];

    const int o = blockIdx.x;
    const int t = threadIdx.x;

    for (int idx = t; idx < LTOK * 64; idx += 288) {
        int l = idx >> 6, i = idx & 63;
        int w_ = l / 9, p = l - w_ * 9;
        sm_a[idx] = conv_w[(((w_ * 64 + o) * 64 + i) * 9) + p];
    }
    __syncthreads();

    if (t < 192) {
        float wrow[64];
#pragma unroll
        for (int i = 0; i < 64; i++) wrow[i] = w_qkv[t * 64 + i];
        const float bj = b_qkv[t];
        for (int l = 0; l < LTOK; l++) {
            float acc = bj;
#pragma unroll
            for (int i = 0; i < 64; i++) acc += sm_a[l * 64 + i] * wrow[i];
            sm_qkv[l * 192 + t] = acc;
        }
    }
    __syncthreads();

    {
        const int h = t / LTOK;
        const int l = t - h * LTOK;
        const float scale = 0.3535533905932738f;
        float sc[LTOK];
        float mx = -1e30f;
#pragma unroll
        for (int m = 0; m < LTOK; m++) {
            float s_ = 0.f;
#pragma unroll
            for (int d = 0; d < DHD; d++)
                s_ += sm_qkv[l * 192 + h * 8 + d] * sm_qkv[m * 192 + 64 + h * 8 + d];
            sc[m] = s_ * scale;
            mx = fmaxf(mx, sc[m]);
        }
        float denom = 0.f;
#pragma unroll
        for (int m = 0; m < LTOK; m++) { sc[m] = expf(sc[m] - mx); denom += sc[m]; }
        const float inv = 1.f / denom;
        float ov[DHD];
#pragma unroll
        for (int d = 0; d < DHD; d++) ov[d] = 0.f;
#pragma unroll
        for (int m = 0; m < LTOK; m++) {
            const float p_ = sc[m];
#pragma unroll
            for (int d = 0; d < DHD; d++)
                ov[d] += p_ * sm_qkv[m * 192 + 128 + h * 8 + d];
        }
#pragma unroll
        for (int d = 0; d < DHD; d++)
            sm_a[l * 64 + h * 8 + d] = ov[d] * inv;
    }
    __syncthreads();

    if (t < 64) {
        const float bj = b_out[t];
        for (int l = 0; l < LTOK; l++) {
            float acc = bj;
#pragma unroll
            for (int c = 0; c < 64; c++) acc += sm_a[l * 64 + c] * w_out[t * 64 + c];
            sm_k1[l * 64 + t] = acc;
        }
    }
    __syncthreads();

    for (int w_ = 0; w_ < WINS; w_++) {
        if (t < 64) {
            float pl = 0.f;
#pragma unroll
            for (int p = 0; p < 9; p++) pl += sm_k1[(w_ * 9 + p) * 64 + t];
            sm_pooled[t] = pl * (1.f / 9.f);
        }
        __syncthreads();
        if (t < 4) {
            float a = se_b1[w_ * 4 + t];
            for (int i = 0; i < 64; i++)
                a += sm_pooled[i] * se_w1[(w_ * 4 + t) * 64 + i];
            sm_h1[t] = fmaxf(a, 0.f);
        }
        __syncthreads();
        if (t < 64) {   // t = ci (global)
            float z = se_b2[w_ * 64 + t];
#pragma unroll
            for (int r = 0; r < 4; r++) z += sm_h1[r] * se_w2[(w_ * 64 + t) * 4 + r];
            const float s_ = 1.f / (1.f + expf(-z));
            const int chunk = t >> 4, k = t & 15;
            const int j = (k & 7) >> 1;
            const int pos = 4 * j + (k & 1) + ((k >> 3) << 1);
#pragma unroll
            for (int p = 0; p < 9; p++) {
                float vv = sm_k1[(w_ * 9 + p) * 64 + t] * s_;
                __nv_bfloat16 h = __float2bfloat16(vv);
                __nv_bfloat16 l = __float2bfloat16(vv - __bfloat162float(h));
                size_t base = ((size_t)((w_ * 4 + chunk) * 9 + p) * 2) * 1024
                              + (size_t)o * 16 + pos;
                g_wB[base] = h;           // hl = 0
                g_wB[base + 1024] = l;    // hl = 1
            }
        }
        __syncthreads();
    }
}

// ===========================================================================
// Kernel B: mma.sync implicit-GEMM conv + LN + residual.
// CTA = (strip of 2 rows, win, b); 256 thr; warp = (row r = wid/4, quarter qt):
// 32 px x 64 co, acc[2 mt][8 nt][4]. 3 passes bf16 hi/lo.
// ===========================================================================
__global__ void __launch_bounds__(256, 2) conv_ln(
    const float* __restrict__ x,
    const float* __restrict__ ln_w,
    const float* __restrict__ ln_b,
    float* __restrict__ out)
{
    __shared__ __align__(16) char smem[33792];   // X stage (2*4*132*16 bf16) / epilogue buf (64*132 f32)
    __shared__ float lnw[64], lnb[64];

    const int b  = blockIdx.z;
    const int w_ = blockIdx.y;
    const int wy = w_ >> 1, wx = w_ & 1;
    const int y0 = blockIdx.x << 1;        // window-local row of this strip
    const int t  = threadIdx.x;
    const int wid = t >> 5, lane = t & 31;
    const int r  = wid >> 2, qt = wid & 3;

    if (t < 64) { lnw[t] = ln_w[t]; lnb[t] = ln_b[t]; }

    float acc[2][8][4];
#pragma unroll
    for (int mt = 0; mt < 2; mt++)
#pragma unroll
        for (int nt = 0; nt < 8; nt++)
#pragma unroll
            for (int i = 0; i < 4; i++) acc[mt][nt][i] = 0.f;

    const uint32_t sx = smem_u32(smem);
    const int lane16 = lane & 15, lhalf = lane >> 4;

#pragma unroll 1
    for (int c = 0; c < 4; c++) {
        __syncthreads();
        // stage 2 hl x 4 rows (iy = y0-1 .. y0+2), zero rows outside window
        for (int idx = t; idx < 2112; idx += 256) {
            int hl = idx / 1056;
            int rr = idx - hl * 1056;
            int j = rr / 264, k = rr - j * 264;
            int iy = y0 - 1 + j;
            uint4 v = make_uint4(0, 0, 0, 0);
            if ((unsigned)iy < 128u) {
                size_t rowbase = ((((((size_t)hl * 8 + b) * 2 + wx) * 4 + c) * 256
                                  + (size_t)(wy * 128 + iy))) * 264;
                v = ((const uint4*)g_xbf)[rowbase + k];
            }
            ((uint4*)smem)[(hl * 4 + j) * 264 + k] = v;
        }
        __syncthreads();

        const __nv_bfloat16* wbase = g_wB + (size_t)((w_ * 4 + c) * 9) * 2048;
#pragma unroll
        for (int ky = 0; ky < 3; ky++) {
            const int jrow = r + ky;
#pragma unroll
            for (int kx = 0; kx < 3; kx++) {
                // A base address (hl=0): px slot = qt*32 + mt*16 + kx + (lane&15)
                uint32_t arow = sx + (uint32_t)((jrow * 132 + qt * 32 + kx + lane16) * 32)
                                   + (uint32_t)(lhalf << 4);
                const uint2* bp = (const uint2*)(wbase + (size_t)(ky * 3 + kx) * 2048);
                uint32_t ah[8];
                ldmx4(ah,     arow);
                ldmx4(ah + 4, arow + 512);
                // pass 1: Ah * Bh
#pragma unroll
                for (int nt = 0; nt < 8; nt++) {
                    uint2 bf = bp[nt * 32 + lane];
                    mma16816(acc[0][nt], ah,     bf);
                    mma16816(acc[1][nt], ah + 4, bf);
                }
                // pass 2: Ah * Bl
#pragma unroll
                for (int nt = 0; nt < 8; nt++) {
                    uint2 bf = bp[256 + nt * 32 + lane];
                    mma16816(acc[0][nt], ah,     bf);
                    mma16816(acc[1][nt], ah + 4, bf);
                }
                // pass 3: Al * Bh
                ldmx4(ah,     arow + 16896);
                ldmx4(ah + 4, arow + 16896 + 512);
#pragma unroll
                for (int nt = 0; nt < 8; nt++) {
                    uint2 bf = bp[nt * 32 + lane];
                    mma16816(acc[0][nt], ah,     bf);
                    mma16816(acc[1][nt], ah + 4, bf);
                }
            }
        }
    }

    // ---- epilogue: LN in-reg (stats over 64 co), smem transpose, coalesced I/O
    float* buf = (float*)smem;     // [64 co][132 px]
    const int basex = wx << 7;
#pragma unroll 1
    for (int rr = 0; rr < 2; rr++) {
        __syncthreads();
        if (r == rr) {
#pragma unroll
            for (int mt = 0; mt < 2; mt++) {
                float sa = 0.f, sb = 0.f;
#pragma unroll
                for (int nt = 0; nt < 8; nt++) {
                    sa += acc[mt][nt][0] + acc[mt][nt][1];
                    sb += acc[mt][nt][2] + acc[mt][nt][3];
                }
                sa += __shfl_xor_sync(0xffffffffu, sa, 1);
                sa += __shfl_xor_sync(0xffffffffu, sa, 2);
                sb += __shfl_xor_sync(0xffffffffu, sb, 1);
                sb += __shfl_xor_sync(0xffffffffu, sb, 2);
                const float mua = sa * (1.f / 64.f), mub = sb * (1.f / 64.f);
                float va = 0.f, vb = 0.f;
#pragma unroll
                for (int nt = 0; nt < 8; nt++) {
                    float d0 = acc[mt][nt][0] - mua, d1 = acc[mt][nt][1] - mua;
                    float d2 = acc[mt][nt][2] - mub, d3 = acc[mt][nt][3] - mub;
                    va += d0 * d0 + d1 * d1;
                    vb += d2 * d2 + d3 * d3;
                }
                va += __shfl_xor_sync(0xffffffffu, va, 1);
                va += __shfl_xor_sync(0xffffffffu, va, 2);
                vb += __shfl_xor_sync(0xffffffffu, vb, 1);
                vb += __shfl_xor_sync(0xffffffffu, vb, 2);
                const float inva = rsqrtf(va * (1.f / 64.f) + 1e-5f);
                const float invb = rsqrtf(vb * (1.f / 64.f) + 1e-5f);
                const int pxa = qt * 32 + mt * 16 + (lane >> 2);
#pragma unroll
                for (int nt = 0; nt < 8; nt++) {
                    const int co = nt * 8 + ((lane & 3) << 1);
                    buf[co * 132 + pxa]           = (acc[mt][nt][0] - mua) * inva;
                    buf[(co + 1) * 132 + pxa]     = (acc[mt][nt][1] - mua) * inva;
                    buf[co * 132 + pxa + 8]       = (acc[mt][nt][2] - mub) * invb;
                    buf[(co + 1) * 132 + pxa + 8] = (acc[mt][nt][3] - mub) * invb;
                }
            }
        }
        __syncthreads();
        // residual + store, fully coalesced
        {
            const int co = t >> 2, q4 = t & 3;
            const float g = lnw[co], bb_ = lnb[co];
            const int gy = wy * 128 + y0 + rr;
            const size_t gbase = (((size_t)(b * 64 + co)) * 256 + gy) * 256 + basex
                                 + q4 * 32;
            const float* bp2 = &buf[co * 132 + q4 * 32];
#pragma unroll
            for (int i = 0; i < 8; i++) {
                float4 xv = *(const float4*)(x + gbase + i * 4);
                float4 o;
                o.x = xv.x + bp2[i * 4 + 0] * g + bb_;
                o.y = xv.y + bp2[i * 4 + 1] * g + bb_;
                o.z = xv.z + bp2[i * 4 + 2] * g + bb_;
                o.w = xv.w + bp2[i * 4 + 3] * g + bb_;
                *(float4*)(out + gbase + i * 4) = o;
            }
        }
    }
}

// ===========================================================================
extern "C" void kernel_launch(void* const* d_in, const int* in_sizes, int n_in,
                              void* d_out, int out_size)
{
    const float* x      = (const float*)d_in[0];
    const float* conv_w = (const float*)d_in[1];
    const float* w_qkv  = (const float*)d_in[2];
    const float* b_qkv  = (const float*)d_in[3];
    const float* w_out  = (const float*)d_in[4];
    const float* b_out  = (const float*)d_in[5];
    const float* se_w1  = (const float*)d_in[6];
    const float* se_b1  = (const float*)d_in[7];
    const float* se_w2  = (const float*)d_in[8];
    const float* se_b2  = (const float*)d_in[9];
    const float* ln_w   = (const float*)d_in[10];
    const float* ln_b   = (const float*)d_in[11];
    float* out = (float*)d_out;

    prep_x<<<dim3(64, 8, 8), 256>>>(x);
    gen_kernels<<<64, 288>>>(conv_w, w_qkv, b_qkv, w_out, b_out,
                             se_w1, se_b1, se_w2, se_b2);
    conv_ln<<<dim3(64, 4, 8), 256>>>(x, ln_w, ln_b, out);
}

// round 11
// speedup vs baseline: 17.8413x; 1.1214x over previous
#include <cuda_runtime.h>
#include <cuda_bf16.h>
#include <math.h>
#include <cstdint>

#define WINS 4
#define LTOK 36
#define DHD  8

// Weights, mma-B-fragment interleaved: [win][chunk4][tap9][hl2][co64][16] bf16
__device__ __align__(16) __nv_bfloat16 g_wB[4 * 4 * 9 * 2 * 64 * 16];
// X converted: [hl][b][wx2][chunk4][gy256][px132][ci16] bf16 (px slot 0 and 129+ zero)
__device__ __align__(16) __nv_bfloat16 g_xbf[2ULL * 8 * 2 * 4 * 256 * 132 * 16];

// hl=1 offset in uint4 units: 8*2*4*256*132 slots * 2 uint4
#define XLO_U4 4325376ULL

__device__ __forceinline__ uint32_t smem_u32(const void* p) {
    uint32_t a;
    asm("{ .reg .u64 t; cvta.to.shared.u64 t, %1; cvt.u32.u64 %0, t; }" : "=r"(a) : "l"(p));
    return a;
}

__device__ __forceinline__ void ldmx4(uint32_t* r, uint32_t addr) {
    asm volatile("ldmatrix.sync.aligned.m8n8.x4.shared.b16 {%0,%1,%2,%3}, [%4];"
        : "=r"(r[0]), "=r"(r[1]), "=r"(r[2]), "=r"(r[3]) : "r"(addr));
}

__device__ __forceinline__ void mma16816(float* d, const uint32_t* a, uint2 b) {
    asm volatile("mma.sync.aligned.m16n8k16.row.col.f32.bf16.bf16.f32 "
        "{%0,%1,%2,%3}, {%4,%5,%6,%7}, {%8,%9}, {%0,%1,%2,%3};"
        : "+f"(d[0]), "+f"(d[1]), "+f"(d[2]), "+f"(d[3])
        : "r"(a[0]), "r"(a[1]), "r"(a[2]), "r"(a[3]), "r"(b.x), "r"(b.y));
}

// ===========================================================================
// Kernel P: x -> bf16 hi/lo, direct (no smem). Thread = one px slot.
// Grid (256 gy, 8 = wx*4+c, 8 b), block 160 (132 active).
// ===========================================================================
__global__ void __launch_bounds__(160) prep_x(const float* __restrict__ x)
{
    const int b  = blockIdx.z;
    const int wx = blockIdx.y >> 2;
    const int c  = blockIdx.y & 3;
    const int gy = blockIdx.x;
    const int px = threadIdx.x;
    if (px >= 132) return;

    const bool in = (px >= 1 && px <= 128);
    const float* xp = x + (((size_t)(b * 64 + c * 16)) * 256 + gy) * 256
                        + wx * 128 + px - 1;
    float v[16];
#pragma unroll
    for (int ci = 0; ci < 16; ci++)
        v[ci] = in ? xp[(size_t)ci * 65536] : 0.f;

    uint32_t hw[8], lw[8];
#pragma unroll
    for (int j = 0; j < 8; j++) {
        float a = v[2 * j], bb = v[2 * j + 1];
        __nv_bfloat16 ha = __float2bfloat16(a);
        __nv_bfloat16 hb = __float2bfloat16(bb);
        __nv_bfloat16 la = __float2bfloat16(a - __bfloat162float(ha));
        __nv_bfloat16 lb = __float2bfloat16(bb - __bfloat162float(hb));
        hw[j] = (uint32_t)__bfloat16_as_ushort(ha) | ((uint32_t)__bfloat16_as_ushort(hb) << 16);
        lw[j] = (uint32_t)__bfloat16_as_ushort(la) | ((uint32_t)__bfloat16_as_ushort(lb) << 16);
    }
    const size_t slot = ((((size_t)b * 2 + wx) * 4 + c) * 256 + gy) * 132 + px;
    uint4* dh = (uint4*)g_xbf + slot * 2;
    uint4* dl = dh + XLO_U4;
    dh[0] = make_uint4(hw[0], hw[1], hw[2], hw[3]);
    dh[1] = make_uint4(hw[4], hw[5], hw[6], hw[7]);
    dl[0] = make_uint4(lw[0], lw[1], lw[2], lw[3]);
    dl[1] = make_uint4(lw[4], lw[5], lw[6], lw[7]);
}

// ===========================================================================
// Kernel A: attention + SE -> bf16 hi/lo weights in B-fragment interleave.
// ===========================================================================
__global__ void __launch_bounds__(288) gen_kernels(
    const float* __restrict__ conv_w, const float* __restrict__ w_qkv,
    const float* __restrict__ b_qkv,  const float* __restrict__ w_out,
    const float* __restrict__ b_out,  const float* __restrict__ se_w1,
    const float* __restrict__ se_b1,  const float* __restrict__ se_w2,
    const float* __restrict__ se_b2)
{
    __shared__ float sm_a[LTOK * 64];
    __shared__ float sm_qkv[LTOK * 192];
    __shared__ float sm_k1[LTOK * 64];
    __shared__ float sm_pooled[64];
    __shared__ float sm_h1[4];

    const int o = blockIdx.x;
    const int t = threadIdx.x;

    for (int idx = t; idx < LTOK * 64; idx += 288) {
        int l = idx >> 6, i = idx & 63;
        int w_ = l / 9, p = l - w_ * 9;
        sm_a[idx] = conv_w[(((w_ * 64 + o) * 64 + i) * 9) + p];
    }
    __syncthreads();

    if (t < 192) {
        float wrow[64];
#pragma unroll
        for (int i = 0; i < 64; i++) wrow[i] = w_qkv[t * 64 + i];
        const float bj = b_qkv[t];
        for (int l = 0; l < LTOK; l++) {
            float acc = bj;
#pragma unroll
            for (int i = 0; i < 64; i++) acc += sm_a[l * 64 + i] * wrow[i];
            sm_qkv[l * 192 + t] = acc;
        }
    }
    __syncthreads();

    {
        const int h = t / LTOK;
        const int l = t - h * LTOK;
        const float scale = 0.3535533905932738f;
        float sc[LTOK];
        float mx = -1e30f;
#pragma unroll
        for (int m = 0; m < LTOK; m++) {
            float s_ = 0.f;
#pragma unroll
            for (int d = 0; d < DHD; d++)
                s_ += sm_qkv[l * 192 + h * 8 + d] * sm_qkv[m * 192 + 64 + h * 8 + d];
            sc[m] = s_ * scale;
            mx = fmaxf(mx, sc[m]);
        }
        float denom = 0.f;
#pragma unroll
        for (int m = 0; m < LTOK; m++) { sc[m] = expf(sc[m] - mx); denom += sc[m]; }
        const float inv = 1.f / denom;
        float ov[DHD];
#pragma unroll
        for (int d = 0; d < DHD; d++) ov[d] = 0.f;
#pragma unroll
        for (int m = 0; m < LTOK; m++) {
            const float p_ = sc[m];
#pragma unroll
            for (int d = 0; d < DHD; d++)
                ov[d] += p_ * sm_qkv[m * 192 + 128 + h * 8 + d];
        }
#pragma unroll
        for (int d = 0; d < DHD; d++)
            sm_a[l * 64 + h * 8 + d] = ov[d] * inv;
    }
    __syncthreads();

    if (t < 64) {
        const float bj = b_out[t];
        for (int l = 0; l < LTOK; l++) {
            float acc = bj;
#pragma unroll
            for (int c = 0; c < 64; c++) acc += sm_a[l * 64 + c] * w_out[t * 64 + c];
            sm_k1[l * 64 + t] = acc;
        }
    }
    __syncthreads();

    for (int w_ = 0; w_ < WINS; w_++) {
        if (t < 64) {
            float pl = 0.f;
#pragma unroll
            for (int p = 0; p < 9; p++) pl += sm_k1[(w_ * 9 + p) * 64 + t];
            sm_pooled[t] = pl * (1.f / 9.f);
        }
        __syncthreads();
        if (t < 4) {
            float a = se_b1[w_ * 4 + t];
            for (int i = 0; i < 64; i++)
                a += sm_pooled[i] * se_w1[(w_ * 4 + t) * 64 + i];
            sm_h1[t] = fmaxf(a, 0.f);
        }
        __syncthreads();
        if (t < 64) {   // t = ci (global)
            float z = se_b2[w_ * 64 + t];
#pragma unroll
            for (int r = 0; r < 4; r++) z += sm_h1[r] * se_w2[(w_ * 64 + t) * 4 + r];
            const float s_ = 1.f / (1.f + expf(-z));
            const int chunk = t >> 4, k = t & 15;
            const int j = (k & 7) >> 1;
            const int pos = 4 * j + (k & 1) + ((k >> 3) << 1);
#pragma unroll
            for (int p = 0; p < 9; p++) {
                float vv = sm_k1[(w_ * 9 + p) * 64 + t] * s_;
                __nv_bfloat16 h = __float2bfloat16(vv);
                __nv_bfloat16 l = __float2bfloat16(vv - __bfloat162float(h));
                size_t base = ((size_t)((w_ * 4 + chunk) * 9 + p) * 2) * 1024
                              + (size_t)o * 16 + pos;
                g_wB[base] = h;           // hl = 0
                g_wB[base + 1024] = l;    // hl = 1
            }
        }
        __syncthreads();
    }
}

// ===========================================================================
// Kernel B: mma.sync implicit-GEMM conv + LN + residual.
// CTA = (strip of 2 rows, win, b); 256 thr; warp = (row r, px quarter qt).
// B fragments loaded ONCE per (tap, nt): 6 MMAs per Bh/Bl pair.
// ===========================================================================
__global__ void __launch_bounds__(256, 2) conv_ln(
    const float* __restrict__ x,
    const float* __restrict__ ln_w,
    const float* __restrict__ ln_b,
    float* __restrict__ out)
{
    __shared__ __align__(16) char smem[33792];
    __shared__ float lnw[64], lnb[64];

    const int b  = blockIdx.z;
    const int w_ = blockIdx.y;
    const int wy = w_ >> 1, wx = w_ & 1;
    const int y0 = blockIdx.x << 1;
    const int t  = threadIdx.x;
    const int wid = t >> 5, lane = t & 31;
    const int r  = wid >> 2, qt = wid & 3;

    if (t < 64) { lnw[t] = ln_w[t]; lnb[t] = ln_b[t]; }

    float acc[2][8][4];
#pragma unroll
    for (int mt = 0; mt < 2; mt++)
#pragma unroll
        for (int nt = 0; nt < 8; nt++)
#pragma unroll
            for (int i = 0; i < 4; i++) acc[mt][nt][i] = 0.f;

    const uint32_t sx = smem_u32(smem);
    const int lane16 = lane & 15, lhalf = lane >> 4;

#pragma unroll 1
    for (int c = 0; c < 4; c++) {
        __syncthreads();
        // stage 2 hl x 4 rows (iy = y0-1 .. y0+2), zero rows outside window
        for (int idx = t; idx < 2112; idx += 256) {
            int hl = idx / 1056;
            int rr = idx - hl * 1056;
            int j = rr / 264, k = rr - j * 264;
            int iy = y0 - 1 + j;
            uint4 v = make_uint4(0, 0, 0, 0);
            if ((unsigned)iy < 128u) {
                size_t slot = ((((size_t)b * 2 + wx) * 4 + c) * 256
                               + (size_t)(wy * 128 + iy)) * 132;
                v = (((const uint4*)g_xbf) + hl * XLO_U4)[slot * 2 + k];
            }
            ((uint4*)smem)[(hl * 4 + j) * 264 + k] = v;
        }
        __syncthreads();

        const __nv_bfloat16* wbase = g_wB + (size_t)((w_ * 4 + c) * 9) * 2048;
#pragma unroll
        for (int ky = 0; ky < 3; ky++) {
            const int jrow = r + ky;
#pragma unroll
            for (int kx = 0; kx < 3; kx++) {
                uint32_t arow = sx + (uint32_t)((jrow * 132 + qt * 32 + kx + lane16) * 32)
                                   + (uint32_t)(lhalf << 4);
                const uint2* bp = (const uint2*)(wbase + (size_t)(ky * 3 + kx) * 2048);
                uint32_t ah[8], al[8];
                ldmx4(ah,     arow);
                ldmx4(ah + 4, arow + 512);
                ldmx4(al,     arow + 16896);
                ldmx4(al + 4, arow + 16896 + 512);
#pragma unroll
                for (int nt = 0; nt < 8; nt++) {
                    uint2 bfh = bp[nt * 32 + lane];
                    uint2 bfl = bp[256 + nt * 32 + lane];
                    mma16816(acc[0][nt], ah,     bfh);   // hh
                    mma16816(acc[1][nt], ah + 4, bfh);
                    mma16816(acc[0][nt], al,     bfh);   // lh
                    mma16816(acc[1][nt], al + 4, bfh);
                    mma16816(acc[0][nt], ah,     bfl);   // hl
                    mma16816(acc[1][nt], ah + 4, bfl);
                }
            }
        }
    }

    // ---- epilogue: LN stats in-reg, smem transpose, coalesced residual+store
    float* buf = (float*)smem;     // [64 co][132 px]
    const int basex = wx << 7;
#pragma unroll 1
    for (int rr = 0; rr < 2; rr++) {
        __syncthreads();
        if (r == rr) {
#pragma unroll
            for (int mt = 0; mt < 2; mt++) {
                float sa = 0.f, sb = 0.f;
#pragma unroll
                for (int nt = 0; nt < 8; nt++) {
                    sa += acc[mt][nt][0] + acc[mt][nt][1];
                    sb += acc[mt][nt][2] + acc[mt][nt][3];
                }
                sa += __shfl_xor_sync(0xffffffffu, sa, 1);
                sa += __shfl_xor_sync(0xffffffffu, sa, 2);
                sb += __shfl_xor_sync(0xffffffffu, sb, 1);
                sb += __shfl_xor_sync(0xffffffffu, sb, 2);
                const float mua = sa * (1.f / 64.f), mub = sb * (1.f / 64.f);
                float va = 0.f, vb = 0.f;
#pragma unroll
                for (int nt = 0; nt < 8; nt++) {
                    float d0 = acc[mt][nt][0] - mua, d1 = acc[mt][nt][1] - mua;
                    float d2 = acc[mt][nt][2] - mub, d3 = acc[mt][nt][3] - mub;
                    va += d0 * d0 + d1 * d1;
                    vb += d2 * d2 + d3 * d3;
                }
                va += __shfl_xor_sync(0xffffffffu, va, 1);
                va += __shfl_xor_sync(0xffffffffu, va, 2);
                vb += __shfl_xor_sync(0xffffffffu, vb, 1);
                vb += __shfl_xor_sync(0xffffffffu, vb, 2);
                const float inva = rsqrtf(va * (1.f / 64.f) + 1e-5f);
                const float invb = rsqrtf(vb * (1.f / 64.f) + 1e-5f);
                const int pxa = qt * 32 + mt * 16 + (lane >> 2);
#pragma unroll
                for (int nt = 0; nt < 8; nt++) {
                    const int co = nt * 8 + ((lane & 3) << 1);
                    buf[co * 132 + pxa]           = (acc[mt][nt][0] - mua) * inva;
                    buf[(co + 1) * 132 + pxa]     = (acc[mt][nt][1] - mua) * inva;
                    buf[co * 132 + pxa + 8]       = (acc[mt][nt][2] - mub) * invb;
                    buf[(co + 1) * 132 + pxa + 8] = (acc[mt][nt][3] - mub) * invb;
                }
            }
        }
        __syncthreads();
        {
            const int co = t >> 2, q4 = t & 3;
            const float g = lnw[co], bb_ = lnb[co];
            const int gy = wy * 128 + y0 + rr;
            const size_t gbase = (((size_t)(b * 64 + co)) * 256 + gy) * 256 + basex
                                 + q4 * 32;
            const float* bp2 = &buf[co * 132 + q4 * 32];
#pragma unroll
            for (int i = 0; i < 8; i++) {
                float4 xv = *(const float4*)(x + gbase + i * 4);
                float4 o;
                o.x = xv.x + bp2[i * 4 + 0] * g + bb_;
                o.y = xv.y + bp2[i * 4 + 1] * g + bb_;
                o.z = xv.z + bp2[i * 4 + 2] * g + bb_;
                o.w = xv.w + bp2[i * 4 + 3] * g + bb_;
                *(float4*)(out + gbase + i * 4) = o;
            }
        }
    }
}

// ===========================================================================
extern "C" void kernel_launch(void* const* d_in, const int* in_sizes, int n_in,
                              void* d_out, int out_size)
{
    const float* x      = (const float*)d_in[0];
    const float* conv_w = (const float*)d_in[1];
    const float* w_qkv  = (const float*)d_in[2];
    const float* b_qkv  = (const float*)d_in[3];
    const float* w_out  = (const float*)d_in[4];
    const float* b_out  = (const float*)d_in[5];
    const float* se_w1  = (const float*)d_in[6];
    const float* se_b1  = (const float*)d_in[7];
    const float* se_w2  = (const float*)d_in[8];
    const float* se_b2  = (const float*)d_in[9];
    const float* ln_w   = (const float*)d_in[10];
    const float* ln_b   = (const float*)d_in[11];
    float* out = (float*)d_out;

    prep_x<<<dim3(256, 8, 8), 160>>>(x);
    gen_kernels<<<64, 288>>>(conv_w, w_qkv, b_qkv, w_out, b_out,
                             se_w1, se_b1, se_w2, se_b2);
    conv_ln<<<dim3(64, 4, 8), 256>>>(x, ln_w, ln_b, out);
}